// round 16
// baseline (speedup 1.0000x reference)
#include <cuda_runtime.h>
#include <cuda_fp16.h>
#include <math.h>
#include <stdint.h>

// Problem constants (fixed by the dataset)
#define NN      50000
#define EE_MAX  500000
#define ET_MAX  (NN + EE_MAX)
#define IND     384
#define HID1    1024   // 4 heads * 256
#define C1      256
#define H1      4
#define C2      128
#define NEG_SLOPE 0.2f

// transposed-weight buffer offsets (halves)
#define OFF_ENC 0
#define CNT_ENC (384 * 384)
#define OFF_W1  (CNT_ENC)
#define CNT_W1  (384 * 1024)
#define OFF_W2  (OFF_W1 + CNT_W1)
#define CNT_W2  (1024 * 128)
#define CNT_WC  (OFF_W2 + CNT_W2)

// ---------------- scratch (static device globals; no allocation) -------------
static __device__ __align__(16) __half g_xh  [(size_t)NN * IND];   // x -> fp16
static __device__ __align__(16) __half g_h0h [(size_t)NN * IND];   // encoder out (fp16)
static __device__ __align__(16) __half g_h1h [(size_t)NN * HID1];  // GAT1 GEMM out (fp16)
static __device__ __align__(16) __half g_o1h [(size_t)NN * HID1];  // layer-1 output (fp16)
static __device__ __align__(16) __half g_h2h [(size_t)NN * C2];    // GAT2 GEMM out (fp16)
static __device__ __align__(16) __half g_wth [CNT_WC];             // transposed fp16 weights

static __device__ __align__(16) float g_as1[NN * H1];
static __device__ __align__(16) float g_ad1[NN * H1];
static __device__ float g_as2[NN];
static __device__ float g_ad2[NN];

static __device__ __align__(16) float g_w1[(size_t)ET_MAX * H1];
static __device__ float g_w2[ET_MAX];

static __device__ int g_src[ET_MAX];
static __device__ int g_dst[ET_MAX];
static __device__ int g_deg[NN];
static __device__ int g_cursor[NN];
static __device__ int g_rowstart[NN + 1];
static __device__ int g_csr_src[ET_MAX];
static __device__ int g_is64;

// ---------------- mma helpers -------------------------------------------------
__device__ __forceinline__ void mma_f16(float* c, const uint32_t* a, const uint32_t* b) {
    asm volatile(
        "mma.sync.aligned.m16n8k16.row.col.f32.f16.f16.f32 "
        "{%0,%1,%2,%3},{%4,%5,%6,%7},{%8,%9},{%0,%1,%2,%3};"
        : "+f"(c[0]), "+f"(c[1]), "+f"(c[2]), "+f"(c[3])
        : "r"(a[0]), "r"(a[1]), "r"(a[2]), "r"(a[3]), "r"(b[0]), "r"(b[1]));
}

__device__ __forceinline__ void ldsm_x4(uint32_t* d, uint32_t addr) {
    asm volatile("ldmatrix.sync.aligned.m8n8.x4.shared.b16 {%0,%1,%2,%3}, [%4];"
        : "=r"(d[0]), "=r"(d[1]), "=r"(d[2]), "=r"(d[3]) : "r"(addr));
}

// ---------------- small kernels -----------------------------------------------

// zero deg/cursor; thread 0 of block 0 also does int64/int32 detection
__global__ void k_init(const void* ei, int n) {
    int i = blockIdx.x * blockDim.x + threadIdx.x;
    if (i == 0) {
        const unsigned int* u = (const unsigned int*)ei;
        int is64 = 1;
        #pragma unroll
        for (int k = 1; k < 16; k += 2)
            if (u[k] != 0u) is64 = 0;
        g_is64 = is64;
    }
    if (i < n) { g_deg[i] = 0; g_cursor[i] = 0; }
}

// Build int32 src/dst lists with self-loops appended; fused degree histogram.
__global__ void k_prep(const void* ei, int E, int n) {
    int i = blockIdx.x * blockDim.x + threadIdx.x;
    int tot = E + n;
    if (i >= tot) return;
    int s, d;
    if (i < E) {
        if (g_is64) {
            const long long* p = (const long long*)ei;
            s = (int)p[i]; d = (int)p[E + i];
        } else {
            const int* p = (const int*)ei;
            s = p[i]; d = p[E + i];
        }
    } else {
        s = d = i - E;
    }
    g_src[i] = s; g_dst[i] = d;
    atomicAdd(&g_deg[d], 1);
}

// fp32 -> fp16, float4-vectorized
__global__ void k_cvt_half(const float* __restrict__ in, __half* __restrict__ out, int n4) {
    int i = blockIdx.x * blockDim.x + threadIdx.x;
    if (i >= n4) return;
    float4 v = ((const float4*)in)[i];
    ((__half2*)out)[i * 2]     = __floats2half2_rn(v.x, v.y);
    ((__half2*)out)[i * 2 + 1] = __floats2half2_rn(v.z, v.w);
}

// Weight transpose + fp16: in [K][N] fp32 row-major -> out [N][K] fp16 row-major
__global__ void k_transpose(const float* __restrict__ in, __half* __restrict__ out,
                            int K, int N) {
    __shared__ float tile[32][33];
    int kb = blockIdx.x * 32, nb = blockIdx.y * 32;
    int tx = threadIdx.x, ty = threadIdx.y;   // 32 x 8
    #pragma unroll
    for (int i = 0; i < 32; i += 8)
        tile[ty + i][tx] = in[(size_t)(kb + ty + i) * N + nb + tx];
    __syncthreads();
    #pragma unroll
    for (int i = 0; i < 32; i += 8)
        out[(size_t)(nb + ty + i) * K + kb + tx] = __float2half_rn(tile[tx][ty + i]);
}

__global__ void __launch_bounds__(1024) k_scan(int n) {
    __shared__ int s_sum[1024];
    int t = threadIdx.x;
    const int CH = (NN + 1023) / 1024;   // 49
    int base = t * CH;
    int sum = 0;
    for (int i = 0; i < CH; i++) {
        int idx = base + i;
        if (idx < n) sum += g_deg[idx];
    }
    s_sum[t] = sum;
    __syncthreads();
    for (int o = 1; o < 1024; o <<= 1) {
        int v = 0;
        if (t >= o) v = s_sum[t - o];
        __syncthreads();
        if (t >= o) s_sum[t] += v;
        __syncthreads();
    }
    int run = (t > 0) ? s_sum[t - 1] : 0;
    for (int i = 0; i < CH; i++) {
        int idx = base + i;
        if (idx < n) { g_rowstart[idx] = run; run += g_deg[idx]; }
    }
    if (t == 1023) g_rowstart[n] = s_sum[1023];
}

__global__ void k_scatter(int tot) {
    int i = blockIdx.x * blockDim.x + threadIdx.x;
    if (i >= tot) return;
    int d = g_dst[i];
    int pos = atomicAdd(&g_cursor[d], 1);
    g_csr_src[g_rowstart[d] + pos] = g_src[i];
}

// ---------------- FP16 tensor-core GEMM (m16n8k16, 2 CTAs/SM, double-buffer) ---
// C[M,N] = A[M,K] @ B[K,N]; A fp16 [M][K], BT fp16 [N][K]. K%32==0, N%128==0.
// MODE 0: write C (fp32, optional) and/or Ch (fp16, optional).
// MODE 1: encoder — add na rank-2 + bias, write Ch only.
template<int MODE>
__global__ void __launch_bounds__(256, 2) k_mma_gemm(
    const __half* __restrict__ A, const __half* __restrict__ BT,
    float* __restrict__ C, __half* __restrict__ Ch, int M, int N, int K,
    const float* __restrict__ e0,   // MODE1: na [M][2]
    const float* __restrict__ e1,   // MODE1: encW rows 384/385 (fp32, stride N)
    const float* __restrict__ e2)   // MODE1: encb
{
    __shared__ uint32_t As[2][128][20];
    __shared__ uint32_t Bs[2][128][20];

    int tid = threadIdx.x;
    int lane = tid & 31;
    int wid = tid >> 5;
    int t = lane & 3;
    int warp_m = wid & 3;     // 32 rows
    int warp_n = wid >> 2;    // 64 cols
    int row0 = blockIdx.y * 128;
    int col0 = blockIdx.x * 128;

    uint32_t as_base = (uint32_t)__cvta_generic_to_shared(&As[0][0][0]);
    uint32_t bs_base = (uint32_t)__cvta_generic_to_shared(&Bs[0][0][0]);
    const uint32_t BUF = 128u * 20u * 4u;   // bytes per buffer

    int a_row = warp_m * 32 + (lane & 15);
    int a_colw = (lane >> 4) * 4;
    int b_row = warp_n * 64 + (lane & 7) + ((lane >> 4) << 3);
    int b_colw = ((lane >> 3) & 1) * 4;

    float acc[2][8][4];
    #pragma unroll
    for (int mt = 0; mt < 2; mt++)
        #pragma unroll
        for (int nt = 0; nt < 8; nt++)
            #pragma unroll
            for (int i = 0; i < 4; i++) acc[mt][nt][i] = 0.f;

    uint4 pa[2], pb[2];
    int nIter = K >> 5;

    // prologue: tile 0 -> regs -> smem buf 0
    #pragma unroll
    for (int i = 0; i < 2; i++) {
        int idx = tid + 256 * i;
        int r = idx >> 2, c = idx & 3;
        int gr = row0 + r;
        pa[i] = (gr < M) ? *(const uint4*)(A + (size_t)gr * K + c * 8)
                         : make_uint4(0u, 0u, 0u, 0u);
        pb[i] = *(const uint4*)(BT + (size_t)(col0 + r) * K + c * 8);
    }
    #pragma unroll
    for (int i = 0; i < 2; i++) {
        int idx = tid + 256 * i;
        int r = idx >> 2, c = idx & 3;
        *(uint4*)&As[0][r][c * 4] = pa[i];
        *(uint4*)&Bs[0][r][c * 4] = pb[i];
    }
    __syncthreads();

    for (int it = 0; it < nIter; it++) {
        int buf = it & 1;
        bool more = (it + 1 < nIter);
        if (more) {
            int k0g = (it + 1) * 32;
            #pragma unroll
            for (int i = 0; i < 2; i++) {
                int idx = tid + 256 * i;
                int r = idx >> 2, c = idx & 3;
                int gr = row0 + r;
                pa[i] = (gr < M) ? *(const uint4*)(A + (size_t)gr * K + k0g + c * 8)
                                 : make_uint4(0u, 0u, 0u, 0u);
                pb[i] = *(const uint4*)(BT + (size_t)(col0 + r) * K + k0g + c * 8);
            }
        }

        uint32_t abase = as_base + buf * BUF;
        uint32_t bbase = bs_base + buf * BUF;
        #pragma unroll
        for (int kk = 0; kk < 2; kk++) {
            uint32_t af[2][4];
            #pragma unroll
            for (int mt = 0; mt < 2; mt++)
                ldsm_x4(af[mt], abase +
                        (uint32_t)((a_row + mt * 16) * 20 + kk * 8 + a_colw) * 4u);
            uint32_t bq[4][4];
            #pragma unroll
            for (int p = 0; p < 4; p++)
                ldsm_x4(bq[p], bbase +
                        (uint32_t)((b_row + p * 16) * 20 + kk * 8 + b_colw) * 4u);
            #pragma unroll
            for (int nt = 0; nt < 8; nt++) {
                uint32_t bf[2] = { bq[nt >> 1][(nt & 1) * 2], bq[nt >> 1][(nt & 1) * 2 + 1] };
                mma_f16(acc[0][nt], af[0], bf);
                mma_f16(acc[1][nt], af[1], bf);
            }
        }

        if (more) {
            int nb = buf ^ 1;
            #pragma unroll
            for (int i = 0; i < 2; i++) {
                int idx = tid + 256 * i;
                int r = idx >> 2, c = idx & 3;
                *(uint4*)&As[nb][r][c * 4] = pa[i];
                *(uint4*)&Bs[nb][r][c * 4] = pb[i];
            }
        }
        __syncthreads();   // single barrier per k-iter
    }

    int g = lane >> 2;
    #pragma unroll
    for (int mt = 0; mt < 2; mt++) {
        int rlo = row0 + warp_m * 32 + mt * 16 + g;
        int rhi = rlo + 8;
        float na_lo0 = 0.f, na_lo1 = 0.f, na_hi0 = 0.f, na_hi1 = 0.f;
        if (MODE == 1) {
            if (rlo < M) { na_lo0 = e0[rlo * 2]; na_lo1 = e0[rlo * 2 + 1]; }
            if (rhi < M) { na_hi0 = e0[rhi * 2]; na_hi1 = e0[rhi * 2 + 1]; }
        }
        #pragma unroll
        for (int nt = 0; nt < 8; nt++) {
            int c = col0 + warp_n * 64 + nt * 8 + 2 * t;
            float v0 = acc[mt][nt][0], v1 = acc[mt][nt][1];
            float v2 = acc[mt][nt][2], v3 = acc[mt][nt][3];
            if (MODE == 1) {
                float w0x = e1[c], w0y = e1[c + 1];
                float w1x = e1[N + c], w1y = e1[N + c + 1];
                float bx = e2[c], by = e2[c + 1];
                v0 += na_lo0 * w0x + na_lo1 * w1x + bx;
                v1 += na_lo0 * w0y + na_lo1 * w1y + by;
                v2 += na_hi0 * w0x + na_hi1 * w1x + bx;
                v3 += na_hi0 * w0y + na_hi1 * w1y + by;
            }
            if (rlo < M) {
                if (MODE == 0 && C)
                    *(float2*)(C + (size_t)rlo * N + c) = make_float2(v0, v1);
                if (Ch)
                    *(__half2*)(Ch + (size_t)rlo * N + c) = __floats2half2_rn(v0, v1);
            }
            if (rhi < M) {
                if (MODE == 0 && C)
                    *(float2*)(C + (size_t)rhi * N + c) = make_float2(v2, v3);
                if (Ch)
                    *(__half2*)(Ch + (size_t)rhi * N + c) = __floats2half2_rn(v2, v3);
            }
        }
    }
}

// alpha_s / alpha_d for layer 1 from fp16 h1: one warp per (node, head)
__global__ void k_alpha1(const float* __restrict__ a_src,
                         const float* __restrict__ a_dst, int n) {
    int w = (blockIdx.x * blockDim.x + threadIdx.x) >> 5;
    int lane = threadIdx.x & 31;
    if (w >= n * H1) return;
    int node = w >> 2, head = w & 3;
    const __half2* hp = (const __half2*)(g_h1h + (size_t)node * HID1 + head * C1);
    const float2* asp = (const float2*)(a_src + head * C1);
    const float2* adp = (const float2*)(a_dst + head * C1);
    float s = 0.f, d = 0.f;
    #pragma unroll
    for (int c2 = lane; c2 < C1 / 2; c2 += 32) {
        float2 v = __half22float2(hp[c2]);
        float2 as = asp[c2];
        float2 ad = adp[c2];
        s += v.x * as.x + v.y * as.y;
        d += v.x * ad.x + v.y * ad.y;
    }
    #pragma unroll
    for (int o = 16; o > 0; o >>= 1) {
        s += __shfl_xor_sync(0xffffffffu, s, o);
        d += __shfl_xor_sync(0xffffffffu, d, o);
    }
    if (lane == 0) { g_as1[node * H1 + head] = s; g_ad1[node * H1 + head] = d; }
}

// alpha_s / alpha_d for layer 2 from fp16 h2: one warp per node
__global__ void k_alpha2(const float* __restrict__ a_src,
                         const float* __restrict__ a_dst, int n) {
    int w = (blockIdx.x * blockDim.x + threadIdx.x) >> 5;
    int lane = threadIdx.x & 31;
    if (w >= n) return;
    const __half2* hp = (const __half2*)(g_h2h + (size_t)w * C2);
    const float2* asp = (const float2*)a_src;
    const float2* adp = (const float2*)a_dst;
    float s = 0.f, d = 0.f;
    #pragma unroll
    for (int c2 = lane; c2 < C2 / 2; c2 += 32) {
        float2 v = __half22float2(hp[c2]);
        float2 as = asp[c2];
        float2 ad = adp[c2];
        s += v.x * as.x + v.y * as.y;
        d += v.x * ad.x + v.y * ad.y;
    }
    #pragma unroll
    for (int o = 16; o > 0; o >>= 1) {
        s += __shfl_xor_sync(0xffffffffu, s, o);
        d += __shfl_xor_sync(0xffffffffu, d, o);
    }
    if (lane == 0) { g_as2[w] = s; g_ad2[w] = d; }
}

__device__ __forceinline__ float leaky(float e) {
    return (e >= 0.f) ? e : NEG_SLOPE * e;
}

// Layer-1 softmax: one warp per dst node; writes NORMALIZED alphas to g_w1.
__global__ void __launch_bounds__(256) k_softmax1() {
    int w = (blockIdx.x * blockDim.x + threadIdx.x) >> 5;
    int lane = threadIdx.x & 31;
    if (w >= NN) return;
    int d = w;
    int beg = g_rowstart[d];
    int deg = g_rowstart[d + 1] - beg;

    float4 ad = *(const float4*)(g_ad1 + d * 4);
    float m0 = -INFINITY, m1 = -INFINITY, m2 = -INFINITY, m3 = -INFINITY;
    for (int j = lane; j < deg; j += 32) {
        int s = g_csr_src[beg + j];
        float4 as = *(const float4*)(g_as1 + s * 4);
        float e0 = leaky(as.x + ad.x);
        float e1 = leaky(as.y + ad.y);
        float e2 = leaky(as.z + ad.z);
        float e3 = leaky(as.w + ad.w);
        *(float4*)(g_w1 + (size_t)(beg + j) * 4) = make_float4(e0, e1, e2, e3);
        m0 = fmaxf(m0, e0); m1 = fmaxf(m1, e1);
        m2 = fmaxf(m2, e2); m3 = fmaxf(m3, e3);
    }
    #pragma unroll
    for (int o = 16; o > 0; o >>= 1) {
        m0 = fmaxf(m0, __shfl_xor_sync(0xffffffffu, m0, o));
        m1 = fmaxf(m1, __shfl_xor_sync(0xffffffffu, m1, o));
        m2 = fmaxf(m2, __shfl_xor_sync(0xffffffffu, m2, o));
        m3 = fmaxf(m3, __shfl_xor_sync(0xffffffffu, m3, o));
    }
    float s0 = 0.f, s1 = 0.f, s2 = 0.f, s3 = 0.f;
    for (int j = lane; j < deg; j += 32) {
        float4 e = *(const float4*)(g_w1 + (size_t)(beg + j) * 4);
        float w0 = __expf(e.x - m0), w1 = __expf(e.y - m1);
        float w2 = __expf(e.z - m2), w3 = __expf(e.w - m3);
        *(float4*)(g_w1 + (size_t)(beg + j) * 4) = make_float4(w0, w1, w2, w3);
        s0 += w0; s1 += w1; s2 += w2; s3 += w3;
    }
    #pragma unroll
    for (int o = 16; o > 0; o >>= 1) {
        s0 += __shfl_xor_sync(0xffffffffu, s0, o);
        s1 += __shfl_xor_sync(0xffffffffu, s1, o);
        s2 += __shfl_xor_sync(0xffffffffu, s2, o);
        s3 += __shfl_xor_sync(0xffffffffu, s3, o);
    }
    float i0 = 1.f / (s0 + 1e-16f), i1 = 1.f / (s1 + 1e-16f);
    float i2 = 1.f / (s2 + 1e-16f), i3 = 1.f / (s3 + 1e-16f);
    for (int j = lane; j < deg; j += 32) {
        float4 ww = *(const float4*)(g_w1 + (size_t)(beg + j) * 4);
        ww.x *= i0; ww.y *= i1; ww.z *= i2; ww.w *= i3;
        *(float4*)(g_w1 + (size_t)(beg + j) * 4) = ww;
    }
}

// Layer-1 aggregation for ONE head (L2-resident slice), fp16 gather, unroll 8.
// 256-thread block = 2 nodes (upper half handles node+1).
__global__ void __launch_bounds__(256) k_agg1h(int head, const float* __restrict__ b1, int n) {
    int d = blockIdx.x * 2 + (threadIdx.x >> 7);
    if (d >= n) return;
    int t = threadIdx.x & 127;
    int beg = g_rowstart[d];
    int deg = g_rowstart[d + 1] - beg;

    const __half2* hb = (const __half2*)g_h1h + head * 128 + t;   // + s*512 per row
    float acc0 = 0.f, acc1 = 0.f;
    int j = 0;
    for (; j + 8 <= deg; j += 8) {
        int ss[8]; float aa[8]; float2 ff[8];
        #pragma unroll
        for (int u = 0; u < 8; u++) {
            ss[u] = g_csr_src[beg + j + u];
            aa[u] = g_w1[(size_t)(beg + j + u) * 4 + head];
        }
        #pragma unroll
        for (int u = 0; u < 8; u++)
            ff[u] = __half22float2(hb[(size_t)ss[u] * 512]);
        #pragma unroll
        for (int u = 0; u < 8; u++) {
            acc0 += ff[u].x * aa[u];
            acc1 += ff[u].y * aa[u];
        }
    }
    for (; j < deg; j++) {
        int s = g_csr_src[beg + j];
        float a = g_w1[(size_t)(beg + j) * 4 + head];
        float2 f = __half22float2(hb[(size_t)s * 512]);
        acc0 += f.x * a;
        acc1 += f.y * a;
    }
    float2 bb = *(const float2*)(b1 + head * C1 + 2 * t);
    float v0 = acc0 + bb.x;
    float v1 = acc1 + bb.y;
    v0 = (v0 > 0.f) ? v0 : expm1f(v0);
    v1 = (v1 > 0.f) ? v1 : expm1f(v1);
    *(__half2*)(g_o1h + (size_t)d * HID1 + head * C1 + 2 * t) = __floats2half2_rn(v0, v1);
}

// Fused layer-2 attention softmax + aggregation + bias -> out.
// 64 threads per node: warp 0 softmax; all 64 gather half2 (2 ch each).
__global__ void __launch_bounds__(64) k_attn_agg2(const float* __restrict__ b2,
                                                  float* __restrict__ out) {
    int d = blockIdx.x;
    int t = threadIdx.x;
    int lane = t & 31;
    int beg = g_rowstart[d];
    int deg = g_rowstart[d + 1] - beg;

    __shared__ float s_inv;

    if (t < 32) {
        float ad = g_ad2[d];
        float m = -INFINITY;
        for (int j = lane; j < deg; j += 32) {
            int s = g_csr_src[beg + j];
            float e = leaky(g_as2[s] + ad);
            g_w2[beg + j] = e;
            m = fmaxf(m, e);
        }
        #pragma unroll
        for (int o = 16; o > 0; o >>= 1)
            m = fmaxf(m, __shfl_xor_sync(0xffffffffu, m, o));
        float sum = 0.f;
        for (int j = lane; j < deg; j += 32) {
            float w = __expf(g_w2[beg + j] - m);
            g_w2[beg + j] = w;
            sum += w;
        }
        #pragma unroll
        for (int o = 16; o > 0; o >>= 1)
            sum += __shfl_xor_sync(0xffffffffu, sum, o);
        if (lane == 0) s_inv = 1.f / (sum + 1e-16f);
    }
    __syncthreads();

    const __half2* hb = (const __half2*)g_h2h + t;   // + s*64 per row
    float acc0 = 0.f, acc1 = 0.f;
    int j = 0;
    for (; j + 8 <= deg; j += 8) {
        int ss[8]; float aa[8]; float2 ff[8];
        #pragma unroll
        for (int u = 0; u < 8; u++) {
            ss[u] = g_csr_src[beg + j + u];
            aa[u] = g_w2[beg + j + u];
        }
        #pragma unroll
        for (int u = 0; u < 8; u++)
            ff[u] = __half22float2(hb[(size_t)ss[u] * 64]);
        #pragma unroll
        for (int u = 0; u < 8; u++) {
            acc0 += ff[u].x * aa[u];
            acc1 += ff[u].y * aa[u];
        }
    }
    for (; j < deg; j++) {
        int s = g_csr_src[beg + j];
        float a = g_w2[beg + j];
        float2 f = __half22float2(hb[(size_t)s * 64]);
        acc0 += f.x * a;
        acc1 += f.y * a;
    }
    float2 bb = *(const float2*)(b2 + 2 * t);
    *(float2*)(out + (size_t)d * C2 + 2 * t) =
        make_float2(acc0 * s_inv + bb.x, acc1 * s_inv + bb.y);
}

// ---------------- host launcher ----------------------------------------------
extern "C" void kernel_launch(void* const* d_in, const int* in_sizes, int n_in,
                              void* d_out, int out_size) {
    const float* x       = (const float*)d_in[0];
    const float* na      = (const float*)d_in[1];
    const void*  ei      = d_in[2];
    const float* encW    = (const float*)d_in[3];
    const float* encb    = (const float*)d_in[4];
    const float* W1      = (const float*)d_in[5];
    const float* a_src1  = (const float*)d_in[6];
    const float* a_dst1  = (const float*)d_in[7];
    const float* b1      = (const float*)d_in[8];
    const float* W2      = (const float*)d_in[9];
    const float* a_src2  = (const float*)d_in[10];
    const float* a_dst2  = (const float*)d_in[11];
    const float* b2      = (const float*)d_in[12];
    float* out = (float*)d_out;

    int n = in_sizes[0] / IND;
    int E = in_sizes[2] / 2;
    int tot = E + n;

    __half *p_xh, *p_h0h, *p_h1h, *p_o1h, *p_h2h, *p_wth;
    cudaGetSymbolAddress((void**)&p_xh, g_xh);
    cudaGetSymbolAddress((void**)&p_h0h, g_h0h);
    cudaGetSymbolAddress((void**)&p_h1h, g_h1h);
    cudaGetSymbolAddress((void**)&p_o1h, g_o1h);
    cudaGetSymbolAddress((void**)&p_h2h, g_h2h);
    cudaGetSymbolAddress((void**)&p_wth, g_wth);

    dim3 tblk(32, 8);

    // launches 1-3; slot 4 = encoder GEMM (profiled by ncu)
    k_transpose<<<dim3(IND / 32, IND / 32), tblk>>>(encW, p_wth + OFF_ENC, IND, IND);
    k_cvt_half<<<(n * (IND / 4) + 255) / 256, 256>>>(x, p_xh, n * (IND / 4));
    k_init<<<(n + 255) / 256, 256>>>(ei, n);
    {
        dim3 grid(IND / 128, (n + 127) / 128);
        k_mma_gemm<1><<<grid, 256>>>(p_xh, p_wth + OFF_ENC, nullptr, p_h0h, n, IND, IND,
                                     na, encW + (size_t)384 * IND, encb);
    }

    // CSR build + remaining transposes
    k_prep<<<(tot + 255) / 256, 256>>>(ei, E, n);
    k_transpose<<<dim3(IND / 32, HID1 / 32), tblk>>>(W1, p_wth + OFF_W1, IND, HID1);
    k_transpose<<<dim3(HID1 / 32, C2 / 32), tblk>>>(W2, p_wth + OFF_W2, HID1, C2);
    k_scan<<<1, 1024>>>(n);
    k_scatter<<<(tot + 255) / 256, 256>>>(tot);

    // ---- GAT layer 1 (GEMM emits fp16 only) ----
    {
        dim3 grid(HID1 / 128, (n + 127) / 128);
        k_mma_gemm<0><<<grid, 256>>>(p_h0h, p_wth + OFF_W1, nullptr, p_h1h, n, HID1, IND,
                                     nullptr, nullptr, nullptr);
    }
    k_alpha1<<<((n * H1 * 32) + 255) / 256, 256>>>(a_src1, a_dst1, n);
    k_softmax1<<<((n * 32) + 255) / 256, 256>>>();
    for (int h = 0; h < H1; h++)
        k_agg1h<<<(n + 1) / 2, 256>>>(h, b1, n);

    // ---- GAT layer 2 (fp16 h2) ----
    {
        dim3 grid(C2 / 128, (n + 127) / 128);
        k_mma_gemm<0><<<grid, 256>>>(p_o1h, p_wth + OFF_W2, nullptr, p_h2h, n, C2, HID1,
                                     nullptr, nullptr, nullptr);
    }
    k_alpha2<<<((n * 32) + 127) / 128, 128>>>(a_src2, a_dst2, n);
    k_attn_agg2<<<n, 64>>>(b2, out);
}

// round 17
// speedup vs baseline: 1.1432x; 1.1432x over previous
#include <cuda_runtime.h>
#include <cuda_fp16.h>
#include <math.h>
#include <stdint.h>

// Problem constants (fixed by the dataset)
#define NN      50000
#define EE_MAX  500000
#define ET_MAX  (NN + EE_MAX)
#define IND     384
#define HID1    1024   // 4 heads * 256
#define C1      256
#define H1      4
#define C2      128
#define NEG_SLOPE 0.2f

// transposed-weight buffer offsets (halves)
#define OFF_ENC 0
#define CNT_ENC (384 * 384)
#define OFF_W1  (CNT_ENC)
#define CNT_W1  (384 * 1024)
#define OFF_W2  (OFF_W1 + CNT_W1)
#define CNT_W2  (1024 * 128)
#define CNT_WC  (OFF_W2 + CNT_W2)

// ---------------- scratch (static device globals; no allocation) -------------
static __device__ __align__(16) __half g_xh  [(size_t)NN * IND];   // x -> fp16
static __device__ __align__(16) __half g_h0h [(size_t)NN * IND];   // encoder out (fp16)
static __device__ __align__(16) __half g_h1h [(size_t)NN * HID1];  // GAT1 GEMM out (fp16)
static __device__ __align__(16) __half g_o1h [(size_t)NN * HID1];  // layer-1 output (fp16)
static __device__ __align__(16) __half g_h2h [(size_t)NN * C2];    // GAT2 GEMM out (fp16)
static __device__ __align__(16) __half g_wth [CNT_WC];             // transposed fp16 weights

static __device__ __align__(16) float g_as1[NN * H1];
static __device__ __align__(16) float g_ad1[NN * H1];
static __device__ float g_as2[NN];
static __device__ float g_ad2[NN];

static __device__ __align__(16) float g_w1[(size_t)ET_MAX * H1];
static __device__ float g_w2[ET_MAX];

static __device__ int g_src[ET_MAX];
static __device__ int g_dst[ET_MAX];
static __device__ int g_deg[NN];
static __device__ int g_cursor[NN];
static __device__ int g_rowstart[NN + 1];
static __device__ int g_csr_src[ET_MAX];
static __device__ int g_is64;

// ---------------- mma helpers -------------------------------------------------
__device__ __forceinline__ void mma_f16(float* c, const uint32_t* a, const uint32_t* b) {
    asm volatile(
        "mma.sync.aligned.m16n8k16.row.col.f32.f16.f16.f32 "
        "{%0,%1,%2,%3},{%4,%5,%6,%7},{%8,%9},{%0,%1,%2,%3};"
        : "+f"(c[0]), "+f"(c[1]), "+f"(c[2]), "+f"(c[3])
        : "r"(a[0]), "r"(a[1]), "r"(a[2]), "r"(a[3]), "r"(b[0]), "r"(b[1]));
}

__device__ __forceinline__ void ldsm_x4(uint32_t* d, uint32_t addr) {
    asm volatile("ldmatrix.sync.aligned.m8n8.x4.shared.b16 {%0,%1,%2,%3}, [%4];"
        : "=r"(d[0]), "=r"(d[1]), "=r"(d[2]), "=r"(d[3]) : "r"(addr));
}

// ---------------- small kernels -----------------------------------------------

// zero deg/cursor; thread 0 of block 0 also does int64/int32 detection
__global__ void k_init(const void* ei, int n) {
    int i = blockIdx.x * blockDim.x + threadIdx.x;
    if (i == 0) {
        const unsigned int* u = (const unsigned int*)ei;
        int is64 = 1;
        #pragma unroll
        for (int k = 1; k < 16; k += 2)
            if (u[k] != 0u) is64 = 0;
        g_is64 = is64;
    }
    if (i < n) { g_deg[i] = 0; g_cursor[i] = 0; }
}

// Build int32 src/dst lists with self-loops appended; fused degree histogram.
__global__ void k_prep(const void* ei, int E, int n) {
    int i = blockIdx.x * blockDim.x + threadIdx.x;
    int tot = E + n;
    if (i >= tot) return;
    int s, d;
    if (i < E) {
        if (g_is64) {
            const long long* p = (const long long*)ei;
            s = (int)p[i]; d = (int)p[E + i];
        } else {
            const int* p = (const int*)ei;
            s = p[i]; d = p[E + i];
        }
    } else {
        s = d = i - E;
    }
    g_src[i] = s; g_dst[i] = d;
    atomicAdd(&g_deg[d], 1);
}

// fp32 -> fp16, float4-vectorized
__global__ void k_cvt_half(const float* __restrict__ in, __half* __restrict__ out, int n4) {
    int i = blockIdx.x * blockDim.x + threadIdx.x;
    if (i >= n4) return;
    float4 v = ((const float4*)in)[i];
    ((__half2*)out)[i * 2]     = __floats2half2_rn(v.x, v.y);
    ((__half2*)out)[i * 2 + 1] = __floats2half2_rn(v.z, v.w);
}

// Weight transpose + fp16: in [K][N] fp32 row-major -> out [N][K] fp16 row-major
__global__ void k_transpose(const float* __restrict__ in, __half* __restrict__ out,
                            int K, int N) {
    __shared__ float tile[32][33];
    int kb = blockIdx.x * 32, nb = blockIdx.y * 32;
    int tx = threadIdx.x, ty = threadIdx.y;   // 32 x 8
    #pragma unroll
    for (int i = 0; i < 32; i += 8)
        tile[ty + i][tx] = in[(size_t)(kb + ty + i) * N + nb + tx];
    __syncthreads();
    #pragma unroll
    for (int i = 0; i < 32; i += 8)
        out[(size_t)(nb + ty + i) * K + kb + tx] = __float2half_rn(tile[tx][ty + i]);
}

__global__ void __launch_bounds__(1024) k_scan(int n) {
    __shared__ int s_sum[1024];
    int t = threadIdx.x;
    const int CH = (NN + 1023) / 1024;   // 49
    int base = t * CH;
    int sum = 0;
    for (int i = 0; i < CH; i++) {
        int idx = base + i;
        if (idx < n) sum += g_deg[idx];
    }
    s_sum[t] = sum;
    __syncthreads();
    for (int o = 1; o < 1024; o <<= 1) {
        int v = 0;
        if (t >= o) v = s_sum[t - o];
        __syncthreads();
        if (t >= o) s_sum[t] += v;
        __syncthreads();
    }
    int run = (t > 0) ? s_sum[t - 1] : 0;
    for (int i = 0; i < CH; i++) {
        int idx = base + i;
        if (idx < n) { g_rowstart[idx] = run; run += g_deg[idx]; }
    }
    if (t == 1023) g_rowstart[n] = s_sum[1023];
}

__global__ void k_scatter(int tot) {
    int i = blockIdx.x * blockDim.x + threadIdx.x;
    if (i >= tot) return;
    int d = g_dst[i];
    int pos = atomicAdd(&g_cursor[d], 1);
    g_csr_src[g_rowstart[d] + pos] = g_src[i];
}

// ---------------- FP16 tensor-core GEMM (m16n8k16, 2 CTAs/SM) ------------------
// C[M,N] = A[M,K] @ B[K,N]; A fp16 [M][K], BT fp16 [N][K]. K%32==0, N%128==0.
// MODE 0: write C (fp32, optional) and/or Ch (fp16, optional).
// MODE 1: encoder — add na rank-2 + bias, write Ch only.
template<int MODE>
__global__ void __launch_bounds__(256, 2) k_mma_gemm(
    const __half* __restrict__ A, const __half* __restrict__ BT,
    float* __restrict__ C, __half* __restrict__ Ch, int M, int N, int K,
    const float* __restrict__ e0,   // MODE1: na [M][2]
    const float* __restrict__ e1,   // MODE1: encW rows 384/385 (fp32, stride N)
    const float* __restrict__ e2)   // MODE1: encb
{
    __shared__ uint32_t As[128][20];
    __shared__ uint32_t Bs[128][20];

    int tid = threadIdx.x;
    int lane = tid & 31;
    int wid = tid >> 5;
    int t = lane & 3;
    int warp_m = wid & 3;     // 32 rows
    int warp_n = wid >> 2;    // 64 cols
    int row0 = blockIdx.y * 128;
    int col0 = blockIdx.x * 128;

    uint32_t as_base = (uint32_t)__cvta_generic_to_shared(&As[0][0]);
    uint32_t bs_base = (uint32_t)__cvta_generic_to_shared(&Bs[0][0]);

    int a_row = warp_m * 32 + (lane & 15);
    int a_colw = (lane >> 4) * 4;
    int b_row = warp_n * 64 + (lane & 7) + ((lane >> 4) << 3);
    int b_colw = ((lane >> 3) & 1) * 4;

    float acc[2][8][4];
    #pragma unroll
    for (int mt = 0; mt < 2; mt++)
        #pragma unroll
        for (int nt = 0; nt < 8; nt++)
            #pragma unroll
            for (int i = 0; i < 4; i++) acc[mt][nt][i] = 0.f;

    uint4 pa[2], pb[2];
    int nIter = K >> 5;

    #pragma unroll
    for (int i = 0; i < 2; i++) {
        int idx = tid + 256 * i;
        int r = idx >> 2, c = idx & 3;
        int gr = row0 + r;
        pa[i] = (gr < M) ? *(const uint4*)(A + (size_t)gr * K + c * 8)
                         : make_uint4(0u, 0u, 0u, 0u);
        pb[i] = *(const uint4*)(BT + (size_t)(col0 + r) * K + c * 8);
    }
    #pragma unroll
    for (int i = 0; i < 2; i++) {
        int idx = tid + 256 * i;
        int r = idx >> 2, c = idx & 3;
        *(uint4*)&As[r][c * 4] = pa[i];
        *(uint4*)&Bs[r][c * 4] = pb[i];
    }
    __syncthreads();

    for (int it = 0; it < nIter; it++) {
        bool more = (it + 1 < nIter);
        if (more) {
            int k0g = (it + 1) * 32;
            #pragma unroll
            for (int i = 0; i < 2; i++) {
                int idx = tid + 256 * i;
                int r = idx >> 2, c = idx & 3;
                int gr = row0 + r;
                pa[i] = (gr < M) ? *(const uint4*)(A + (size_t)gr * K + k0g + c * 8)
                                 : make_uint4(0u, 0u, 0u, 0u);
                pb[i] = *(const uint4*)(BT + (size_t)(col0 + r) * K + k0g + c * 8);
            }
        }

        #pragma unroll
        for (int kk = 0; kk < 2; kk++) {
            uint32_t af[2][4];
            #pragma unroll
            for (int mt = 0; mt < 2; mt++)
                ldsm_x4(af[mt], as_base +
                        (uint32_t)((a_row + mt * 16) * 20 + kk * 8 + a_colw) * 4u);
            uint32_t bq[4][4];
            #pragma unroll
            for (int p = 0; p < 4; p++)
                ldsm_x4(bq[p], bs_base +
                        (uint32_t)((b_row + p * 16) * 20 + kk * 8 + b_colw) * 4u);
            #pragma unroll
            for (int nt = 0; nt < 8; nt++) {
                uint32_t bf[2] = { bq[nt >> 1][(nt & 1) * 2], bq[nt >> 1][(nt & 1) * 2 + 1] };
                mma_f16(acc[0][nt], af[0], bf);
                mma_f16(acc[1][nt], af[1], bf);
            }
        }

        if (more) {
            __syncthreads();
            #pragma unroll
            for (int i = 0; i < 2; i++) {
                int idx = tid + 256 * i;
                int r = idx >> 2, c = idx & 3;
                *(uint4*)&As[r][c * 4] = pa[i];
                *(uint4*)&Bs[r][c * 4] = pb[i];
            }
            __syncthreads();
        }
    }

    int g = lane >> 2;
    #pragma unroll
    for (int mt = 0; mt < 2; mt++) {
        int rlo = row0 + warp_m * 32 + mt * 16 + g;
        int rhi = rlo + 8;
        float na_lo0 = 0.f, na_lo1 = 0.f, na_hi0 = 0.f, na_hi1 = 0.f;
        if (MODE == 1) {
            if (rlo < M) { na_lo0 = e0[rlo * 2]; na_lo1 = e0[rlo * 2 + 1]; }
            if (rhi < M) { na_hi0 = e0[rhi * 2]; na_hi1 = e0[rhi * 2 + 1]; }
        }
        #pragma unroll
        for (int nt = 0; nt < 8; nt++) {
            int c = col0 + warp_n * 64 + nt * 8 + 2 * t;
            float v0 = acc[mt][nt][0], v1 = acc[mt][nt][1];
            float v2 = acc[mt][nt][2], v3 = acc[mt][nt][3];
            if (MODE == 1) {
                float w0x = e1[c], w0y = e1[c + 1];
                float w1x = e1[N + c], w1y = e1[N + c + 1];
                float bx = e2[c], by = e2[c + 1];
                v0 += na_lo0 * w0x + na_lo1 * w1x + bx;
                v1 += na_lo0 * w0y + na_lo1 * w1y + by;
                v2 += na_hi0 * w0x + na_hi1 * w1x + bx;
                v3 += na_hi0 * w0y + na_hi1 * w1y + by;
            }
            if (rlo < M) {
                if (MODE == 0 && C)
                    *(float2*)(C + (size_t)rlo * N + c) = make_float2(v0, v1);
                if (Ch)
                    *(__half2*)(Ch + (size_t)rlo * N + c) = __floats2half2_rn(v0, v1);
            }
            if (rhi < M) {
                if (MODE == 0 && C)
                    *(float2*)(C + (size_t)rhi * N + c) = make_float2(v2, v3);
                if (Ch)
                    *(__half2*)(Ch + (size_t)rhi * N + c) = __floats2half2_rn(v2, v3);
            }
        }
    }
}

// alpha_s / alpha_d for layer 1 from fp16 h1: one warp per (node, head)
__global__ void k_alpha1(const float* __restrict__ a_src,
                         const float* __restrict__ a_dst, int n) {
    int w = (blockIdx.x * blockDim.x + threadIdx.x) >> 5;
    int lane = threadIdx.x & 31;
    if (w >= n * H1) return;
    int node = w >> 2, head = w & 3;
    const __half2* hp = (const __half2*)(g_h1h + (size_t)node * HID1 + head * C1);
    const float2* asp = (const float2*)(a_src + head * C1);
    const float2* adp = (const float2*)(a_dst + head * C1);
    float s = 0.f, d = 0.f;
    #pragma unroll
    for (int c2 = lane; c2 < C1 / 2; c2 += 32) {
        float2 v = __half22float2(hp[c2]);
        float2 as = asp[c2];
        float2 ad = adp[c2];
        s += v.x * as.x + v.y * as.y;
        d += v.x * ad.x + v.y * ad.y;
    }
    #pragma unroll
    for (int o = 16; o > 0; o >>= 1) {
        s += __shfl_xor_sync(0xffffffffu, s, o);
        d += __shfl_xor_sync(0xffffffffu, d, o);
    }
    if (lane == 0) { g_as1[node * H1 + head] = s; g_ad1[node * H1 + head] = d; }
}

// alpha_s / alpha_d for layer 2 from fp16 h2: one warp per node
__global__ void k_alpha2(const float* __restrict__ a_src,
                         const float* __restrict__ a_dst, int n) {
    int w = (blockIdx.x * blockDim.x + threadIdx.x) >> 5;
    int lane = threadIdx.x & 31;
    if (w >= n) return;
    const __half2* hp = (const __half2*)(g_h2h + (size_t)w * C2);
    const float2* asp = (const float2*)a_src;
    const float2* adp = (const float2*)a_dst;
    float s = 0.f, d = 0.f;
    #pragma unroll
    for (int c2 = lane; c2 < C2 / 2; c2 += 32) {
        float2 v = __half22float2(hp[c2]);
        float2 as = asp[c2];
        float2 ad = adp[c2];
        s += v.x * as.x + v.y * as.y;
        d += v.x * ad.x + v.y * ad.y;
    }
    #pragma unroll
    for (int o = 16; o > 0; o >>= 1) {
        s += __shfl_xor_sync(0xffffffffu, s, o);
        d += __shfl_xor_sync(0xffffffffu, d, o);
    }
    if (lane == 0) { g_as2[w] = s; g_ad2[w] = d; }
}

__device__ __forceinline__ float leaky(float e) {
    return (e >= 0.f) ? e : NEG_SLOPE * e;
}

// Layer-1 softmax: one warp per dst node; writes NORMALIZED alphas to g_w1.
__global__ void __launch_bounds__(256) k_softmax1() {
    int w = (blockIdx.x * blockDim.x + threadIdx.x) >> 5;
    int lane = threadIdx.x & 31;
    if (w >= NN) return;
    int d = w;
    int beg = g_rowstart[d];
    int deg = g_rowstart[d + 1] - beg;

    float4 ad = *(const float4*)(g_ad1 + d * 4);
    float m0 = -INFINITY, m1 = -INFINITY, m2 = -INFINITY, m3 = -INFINITY;
    for (int j = lane; j < deg; j += 32) {
        int s = g_csr_src[beg + j];
        float4 as = *(const float4*)(g_as1 + s * 4);
        float e0 = leaky(as.x + ad.x);
        float e1 = leaky(as.y + ad.y);
        float e2 = leaky(as.z + ad.z);
        float e3 = leaky(as.w + ad.w);
        *(float4*)(g_w1 + (size_t)(beg + j) * 4) = make_float4(e0, e1, e2, e3);
        m0 = fmaxf(m0, e0); m1 = fmaxf(m1, e1);
        m2 = fmaxf(m2, e2); m3 = fmaxf(m3, e3);
    }
    #pragma unroll
    for (int o = 16; o > 0; o >>= 1) {
        m0 = fmaxf(m0, __shfl_xor_sync(0xffffffffu, m0, o));
        m1 = fmaxf(m1, __shfl_xor_sync(0xffffffffu, m1, o));
        m2 = fmaxf(m2, __shfl_xor_sync(0xffffffffu, m2, o));
        m3 = fmaxf(m3, __shfl_xor_sync(0xffffffffu, m3, o));
    }
    float s0 = 0.f, s1 = 0.f, s2 = 0.f, s3 = 0.f;
    for (int j = lane; j < deg; j += 32) {
        float4 e = *(const float4*)(g_w1 + (size_t)(beg + j) * 4);
        float w0 = __expf(e.x - m0), w1 = __expf(e.y - m1);
        float w2 = __expf(e.z - m2), w3 = __expf(e.w - m3);
        *(float4*)(g_w1 + (size_t)(beg + j) * 4) = make_float4(w0, w1, w2, w3);
        s0 += w0; s1 += w1; s2 += w2; s3 += w3;
    }
    #pragma unroll
    for (int o = 16; o > 0; o >>= 1) {
        s0 += __shfl_xor_sync(0xffffffffu, s0, o);
        s1 += __shfl_xor_sync(0xffffffffu, s1, o);
        s2 += __shfl_xor_sync(0xffffffffu, s2, o);
        s3 += __shfl_xor_sync(0xffffffffu, s3, o);
    }
    float i0 = 1.f / (s0 + 1e-16f), i1 = 1.f / (s1 + 1e-16f);
    float i2 = 1.f / (s2 + 1e-16f), i3 = 1.f / (s3 + 1e-16f);
    for (int j = lane; j < deg; j += 32) {
        float4 ww = *(const float4*)(g_w1 + (size_t)(beg + j) * 4);
        ww.x *= i0; ww.y *= i1; ww.z *= i2; ww.w *= i3;
        *(float4*)(g_w1 + (size_t)(beg + j) * 4) = ww;
    }
}

// Layer-1 aggregation, ALL heads in one pass (fp16 h1 = 100 MB, L2-resident).
// One 256-thread block per node; thread t handles half2 slots t and t+256
// (channels 2t,2t+1 and 512+2t,512+2t+1). Unroll 4 edges.
__global__ void __launch_bounds__(256) k_attn_agg1(const float* __restrict__ b1) {
    int d = blockIdx.x;
    int t = threadIdx.x;
    int beg = g_rowstart[d];
    int deg = g_rowstart[d + 1] - beg;

    int h_lo = t >> 7;            // head for slot t      (0 or 1)
    int h_hi = 2 + h_lo;          // head for slot t+256  (2 or 3)

    const __half2* hb = (const __half2*)g_h1h;
    float a0 = 0.f, a1 = 0.f, a2 = 0.f, a3 = 0.f;   // acc: slot t (.x,.y), slot t+256 (.x,.y)
    int j = 0;
    for (; j + 4 <= deg; j += 4) {
        int ss[4]; float4 ww[4]; float2 flo[4], fhi[4];
        #pragma unroll
        for (int u = 0; u < 4; u++) {
            ss[u] = g_csr_src[beg + j + u];
            ww[u] = *(const float4*)(g_w1 + (size_t)(beg + j + u) * 4);
        }
        #pragma unroll
        for (int u = 0; u < 4; u++) {
            const __half2* row = hb + (size_t)ss[u] * 512;
            flo[u] = __half22float2(row[t]);
            fhi[u] = __half22float2(row[t + 256]);
        }
        #pragma unroll
        for (int u = 0; u < 4; u++) {
            float wlo = h_lo ? ww[u].y : ww[u].x;
            float whi = h_lo ? ww[u].w : ww[u].z;
            a0 += flo[u].x * wlo; a1 += flo[u].y * wlo;
            a2 += fhi[u].x * whi; a3 += fhi[u].y * whi;
        }
    }
    for (; j < deg; j++) {
        int s = g_csr_src[beg + j];
        float4 w = *(const float4*)(g_w1 + (size_t)(beg + j) * 4);
        const __half2* row = hb + (size_t)s * 512;
        float2 flo = __half22float2(row[t]);
        float2 fhi = __half22float2(row[t + 256]);
        float wlo = h_lo ? w.y : w.x;
        float whi = h_lo ? w.w : w.z;
        a0 += flo.x * wlo; a1 += flo.y * wlo;
        a2 += fhi.x * whi; a3 += fhi.y * whi;
    }
    float2 blo = *(const float2*)(b1 + 2 * t);
    float2 bhi = *(const float2*)(b1 + 512 + 2 * t);
    float v0 = a0 + blo.x, v1 = a1 + blo.y;
    float v2 = a2 + bhi.x, v3 = a3 + bhi.y;
    v0 = (v0 > 0.f) ? v0 : expm1f(v0);
    v1 = (v1 > 0.f) ? v1 : expm1f(v1);
    v2 = (v2 > 0.f) ? v2 : expm1f(v2);
    v3 = (v3 > 0.f) ? v3 : expm1f(v3);
    __half2* orow = (__half2*)(g_o1h + (size_t)d * HID1);
    orow[t]       = __floats2half2_rn(v0, v1);
    orow[t + 256] = __floats2half2_rn(v2, v3);
}

// Fused layer-2 attention softmax + aggregation + bias -> out.
// 64 threads per node: warp 0 softmax; all 64 gather half2 (2 ch each).
__global__ void __launch_bounds__(64) k_attn_agg2(const float* __restrict__ b2,
                                                  float* __restrict__ out) {
    int d = blockIdx.x;
    int t = threadIdx.x;
    int lane = t & 31;
    int beg = g_rowstart[d];
    int deg = g_rowstart[d + 1] - beg;

    __shared__ float s_inv;

    if (t < 32) {
        float ad = g_ad2[d];
        float m = -INFINITY;
        for (int j = lane; j < deg; j += 32) {
            int s = g_csr_src[beg + j];
            float e = leaky(g_as2[s] + ad);
            g_w2[beg + j] = e;
            m = fmaxf(m, e);
        }
        #pragma unroll
        for (int o = 16; o > 0; o >>= 1)
            m = fmaxf(m, __shfl_xor_sync(0xffffffffu, m, o));
        float sum = 0.f;
        for (int j = lane; j < deg; j += 32) {
            float w = __expf(g_w2[beg + j] - m);
            g_w2[beg + j] = w;
            sum += w;
        }
        #pragma unroll
        for (int o = 16; o > 0; o >>= 1)
            sum += __shfl_xor_sync(0xffffffffu, sum, o);
        if (lane == 0) s_inv = 1.f / (sum + 1e-16f);
    }
    __syncthreads();

    const __half2* hb = (const __half2*)g_h2h + t;   // + s*64 per row
    float acc0 = 0.f, acc1 = 0.f;
    int j = 0;
    for (; j + 8 <= deg; j += 8) {
        int ss[8]; float aa[8]; float2 ff[8];
        #pragma unroll
        for (int u = 0; u < 8; u++) {
            ss[u] = g_csr_src[beg + j + u];
            aa[u] = g_w2[beg + j + u];
        }
        #pragma unroll
        for (int u = 0; u < 8; u++)
            ff[u] = __half22float2(hb[(size_t)ss[u] * 64]);
        #pragma unroll
        for (int u = 0; u < 8; u++) {
            acc0 += ff[u].x * aa[u];
            acc1 += ff[u].y * aa[u];
        }
    }
    for (; j < deg; j++) {
        int s = g_csr_src[beg + j];
        float a = g_w2[beg + j];
        float2 f = __half22float2(hb[(size_t)s * 64]);
        acc0 += f.x * a;
        acc1 += f.y * a;
    }
    float2 bb = *(const float2*)(b2 + 2 * t);
    *(float2*)(out + (size_t)d * C2 + 2 * t) =
        make_float2(acc0 * s_inv + bb.x, acc1 * s_inv + bb.y);
}

// ---------------- host launcher ----------------------------------------------
extern "C" void kernel_launch(void* const* d_in, const int* in_sizes, int n_in,
                              void* d_out, int out_size) {
    const float* x       = (const float*)d_in[0];
    const float* na      = (const float*)d_in[1];
    const void*  ei      = d_in[2];
    const float* encW    = (const float*)d_in[3];
    const float* encb    = (const float*)d_in[4];
    const float* W1      = (const float*)d_in[5];
    const float* a_src1  = (const float*)d_in[6];
    const float* a_dst1  = (const float*)d_in[7];
    const float* b1      = (const float*)d_in[8];
    const float* W2      = (const float*)d_in[9];
    const float* a_src2  = (const float*)d_in[10];
    const float* a_dst2  = (const float*)d_in[11];
    const float* b2      = (const float*)d_in[12];
    float* out = (float*)d_out;

    int n = in_sizes[0] / IND;
    int E = in_sizes[2] / 2;
    int tot = E + n;

    __half *p_xh, *p_h0h, *p_h1h, *p_o1h, *p_h2h, *p_wth;
    cudaGetSymbolAddress((void**)&p_xh, g_xh);
    cudaGetSymbolAddress((void**)&p_h0h, g_h0h);
    cudaGetSymbolAddress((void**)&p_h1h, g_h1h);
    cudaGetSymbolAddress((void**)&p_o1h, g_o1h);
    cudaGetSymbolAddress((void**)&p_h2h, g_h2h);
    cudaGetSymbolAddress((void**)&p_wth, g_wth);

    dim3 tblk(32, 8);

    // launches 1-3; slot 4 = encoder GEMM (profiled by ncu)
    k_transpose<<<dim3(IND / 32, IND / 32), tblk>>>(encW, p_wth + OFF_ENC, IND, IND);
    k_cvt_half<<<(n * (IND / 4) + 255) / 256, 256>>>(x, p_xh, n * (IND / 4));
    k_init<<<(n + 255) / 256, 256>>>(ei, n);
    {
        dim3 grid(IND / 128, (n + 127) / 128);
        k_mma_gemm<1><<<grid, 256>>>(p_xh, p_wth + OFF_ENC, nullptr, p_h0h, n, IND, IND,
                                     na, encW + (size_t)384 * IND, encb);
    }

    // CSR build + remaining transposes
    k_prep<<<(tot + 255) / 256, 256>>>(ei, E, n);
    k_transpose<<<dim3(IND / 32, HID1 / 32), tblk>>>(W1, p_wth + OFF_W1, IND, HID1);
    k_transpose<<<dim3(HID1 / 32, C2 / 32), tblk>>>(W2, p_wth + OFF_W2, HID1, C2);
    k_scan<<<1, 1024>>>(n);
    k_scatter<<<(tot + 255) / 256, 256>>>(tot);

    // ---- GAT layer 1 ----
    {
        dim3 grid(HID1 / 128, (n + 127) / 128);
        k_mma_gemm<0><<<grid, 256>>>(p_h0h, p_wth + OFF_W1, nullptr, p_h1h, n, HID1, IND,
                                     nullptr, nullptr, nullptr);
    }
    k_alpha1<<<((n * H1 * 32) + 255) / 256, 256>>>(a_src1, a_dst1, n);
    k_softmax1<<<((n * 32) + 255) / 256, 256>>>();
    k_attn_agg1<<<n, 256>>>(b1);

    // ---- GAT layer 2 (fp16 h2) ----
    {
        dim3 grid(C2 / 128, (n + 127) / 128);
        k_mma_gemm<0><<<grid, 256>>>(p_o1h, p_wth + OFF_W2, nullptr, p_h2h, n, C2, HID1,
                                     nullptr, nullptr, nullptr);
    }
    k_alpha2<<<((n * 32) + 127) / 128, 128>>>(a_src2, a_dst2, n);
    k_attn_agg2<<<n, 64>>>(b2, out);
}